// round 6
// baseline (speedup 1.0000x reference)
#include <cuda_runtime.h>
#include <cstdint>

// Flow1 via mma.sync m16n8k8 tf32, 3xTF32 compensation, PRE-SPLIT weights.
// B=262144 rows, Z=128, ZH=64, HS=50 (padded 56), 4 couplings.
// Out: [ z (B*128) | logpz (B) | logqz (B) ] fp32.
//
// presplit_kernel: splits weights into tf32 hi/lo once, padded, pitch-68,
// into __device__ globals. flow_kernel: CTA = 128 rows, 512 thr = 16 warps
// (8 m-groups x 2 n-halves), weights staged to SMEM as raw memcpy.

#define ZZ 128
#define ZH 64
#define HS 50
#define NC 4
#define TPB 512
#define MR 128
#define PZ 68

// gWS per-coupling float offsets
#define GW0H 0
#define GW0L 3808
#define GW1H 7616
#define GW1L 11968
#define GW2H 16320
#define GW2L 20672
#define GWTOT 25024

// smem float offsets
#define OW   0
#define OZ1  25024
#define OZ2  33728
#define OH   42432
#define OB   51136          // b0 @ +0, b1 @ +64, b2 @ +128
#define OQ0  51328
#define OLD  51456          // 2*128
#define OSS  51712          // 2*128
#define SMEM_FLOATS 51968
#define SMEM_BYTES (SMEM_FLOATS * 4)   // 207872

__device__ __align__(16) float gWS[NC][GWTOT];
__device__ float gBB[NC][192];

__device__ __forceinline__ float tanh_fast(float x) {
    float r;
    asm("tanh.approx.f32 %0, %1;" : "=f"(r) : "f"(x));
    return r;
}
__device__ __forceinline__ void split_tf32(float x, uint32_t& hi, uint32_t& lo) {
    asm("cvt.rna.tf32.f32 %0, %1;" : "=r"(hi) : "f"(x));
    float r = x - __uint_as_float(hi);
    asm("cvt.rna.tf32.f32 %0, %1;" : "=r"(lo) : "f"(r));
}
__device__ __forceinline__ void mma8(float (&d)[4], const uint32_t* a,
                                     uint32_t b0, uint32_t b1) {
    asm volatile(
        "mma.sync.aligned.m16n8k8.row.col.f32.tf32.tf32.f32 "
        "{%0,%1,%2,%3}, {%4,%5,%6,%7}, {%8,%9}, {%0,%1,%2,%3};"
        : "+f"(d[0]), "+f"(d[1]), "+f"(d[2]), "+f"(d[3])
        : "r"(a[0]), "r"(a[1]), "r"(a[2]), "r"(a[3]), "r"(b0), "r"(b1));
}

// ---------------- pre-split kernel (one block per coupling) ----------------
__global__ void presplit_kernel(const float* __restrict__ W_in,  const float* __restrict__ b_in,
                                const float* __restrict__ W_mu,  const float* __restrict__ b_mu,
                                const float* __restrict__ W_sig, const float* __restrict__ b_sig)
{
    const int cc = blockIdx.x;
    const int tid = threadIdx.x;
    // W0: target [n<56][k<68], source [HS][ZH]
    for (int idx = tid; idx < 3808; idx += blockDim.x) {
        int n = idx / PZ, k = idx - n * PZ;
        float v = (n < HS && k < ZH) ? W_in[cc * HS * ZH + n * ZH + k] : 0.0f;
        uint32_t h, l;
        split_tf32(v, h, l);
        gWS[cc][GW0H + idx] = __uint_as_float(h);
        gWS[cc][GW0L + idx] = __uint_as_float(l);
    }
    // W1/W2: target [n<64][k<68], source [ZH][HS]
    for (int idx = tid; idx < 4352; idx += blockDim.x) {
        int n = idx / PZ, k = idx - n * PZ;
        float vm = (k < HS) ? W_mu [cc * ZH * HS + n * HS + k] : 0.0f;
        float vs = (k < HS) ? W_sig[cc * ZH * HS + n * HS + k] : 0.0f;
        uint32_t h, l;
        split_tf32(vm, h, l);
        gWS[cc][GW1H + idx] = __uint_as_float(h);
        gWS[cc][GW1L + idx] = __uint_as_float(l);
        split_tf32(vs, h, l);
        gWS[cc][GW2H + idx] = __uint_as_float(h);
        gWS[cc][GW2L + idx] = __uint_as_float(l);
    }
    if (tid < 64) {
        gBB[cc][tid]       = (tid < HS) ? b_in[cc * HS + tid] : 0.0f;
        gBB[cc][64 + tid]  = b_mu [cc * ZH + tid];
        gBB[cc][128 + tid] = b_sig[cc * ZH + tid];
    }
}

// ---------------- main kernel ----------------
__global__ void __launch_bounds__(TPB, 1)
flow_kernel(const float* __restrict__ mean,  const float* __restrict__ logvar,
            const float* __restrict__ eps,
            float* __restrict__ out, int Brows)
{
    extern __shared__ float sm[];
    float* sW0h = sm + OW + GW0H;
    float* sW0l = sm + OW + GW0L;
    float* sW1h = sm + OW + GW1H;
    float* sW1l = sm + OW + GW1L;
    float* sW2h = sm + OW + GW2H;
    float* sW2l = sm + OW + GW2L;
    float* sZ1  = sm + OZ1;
    float* sZ2  = sm + OZ2;
    float* sH   = sm + OH;
    float* sB0  = sm + OB;
    float* sB1  = sm + OB + 64;
    float* sB2  = sm + OB + 128;
    float* sQ0  = sm + OQ0;
    float* sLD  = sm + OLD;
    float* sSS  = sm + OSS;

    const int tid  = threadIdx.x;
    const int lane = tid & 31;
    const int wid  = tid >> 5;
    const int wm   = wid & 7;          // m-group: rows 16*wm..+15
    const int wn   = wid >> 3;         // n-half
    const int gid  = lane >> 2;
    const int tig  = lane & 3;
    const int r0   = 16 * wm + gid;
    const int r1   = r0 + 8;
    const int rowBase = blockIdx.x * MR;

    // ================= reparam =================
    {
        const int rrow = tid >> 2, p = tid & 3;
        float part = 0.0f;
#pragma unroll
        for (int j = 0; j < 8; j++) {
            int q = p + 4 * j;
            size_t g = (size_t)(rowBase + rrow) * 32 + q;
            float4 mv = ((const float4*)mean  )[g];
            float4 lv = ((const float4*)logvar)[g];
            float4 ev = ((const float4*)eps   )[g];
            float4 z4;
            z4.x = fmaf(ev.x, __expf(0.5f * lv.x), mv.x);
            z4.y = fmaf(ev.y, __expf(0.5f * lv.y), mv.y);
            z4.z = fmaf(ev.z, __expf(0.5f * lv.z), mv.z);
            z4.w = fmaf(ev.w, __expf(0.5f * lv.w), mv.w);
            part += lv.x + lv.y + lv.z + lv.w;
            part = fmaf(ev.x, ev.x, part);
            part = fmaf(ev.y, ev.y, part);
            part = fmaf(ev.z, ev.z, part);
            part = fmaf(ev.w, ev.w, part);
            if (q < 16)
                *(float4*)&sZ1[rrow * PZ + 4 * q] = z4;
            else
                *(float4*)&sZ2[rrow * PZ + 4 * (q - 16)] = z4;
        }
        part += __shfl_xor_sync(0xffffffffu, part, 1);
        part += __shfl_xor_sync(0xffffffffu, part, 2);
        if (p == 0) sQ0[rrow] = -0.5f * part;
    }

    float ldp0 = 0.f, ldp1 = 0.f, ssp0 = 0.f, ssp1 = 0.f;

    // ================= couplings =================
#pragma unroll 1
    for (int cc = 0; cc < NC; cc++) {
        // ---- stage pre-split weights: raw float4 memcpy ----
        {
            const float4* src = (const float4*)(&gWS[cc][0]);
            float4* dst = (float4*)(sm + OW);
            for (int i = tid; i < GWTOT / 4; i += TPB) dst[i] = src[i];
            if (tid < 192) sm[OB + tid] = gBB[cc][tid];
        }
        __syncthreads();

        const float* sZa = (cc & 1) ? sZ2 : sZ1;
        float*       sZu = (cc & 1) ? sZ1 : sZ2;

        // ---- GEMM1: H = tanh(Za @ W0^T + b0); N=56 (4/3 split) ----
        {
            const int NT1 = wn ? 3 : 4;
            float acc[4][4] = {};
#pragma unroll
            for (int kt = 0; kt < 8; kt++) {
                uint32_t ah[4], al[4];
                split_tf32(sZa[r0 * PZ + tig +     8 * kt], ah[0], al[0]);
                split_tf32(sZa[r1 * PZ + tig +     8 * kt], ah[1], al[1]);
                split_tf32(sZa[r0 * PZ + tig + 4 + 8 * kt], ah[2], al[2]);
                split_tf32(sZa[r1 * PZ + tig + 4 + 8 * kt], ah[3], al[3]);
#pragma unroll
                for (int nn = 0; nn < 4; nn++) {
                    if (nn >= NT1) break;
                    int nrow = 8 * (wn * 4 + nn) + gid;
                    uint32_t bh0 = __float_as_uint(sW0h[nrow * PZ + tig +     8 * kt]);
                    uint32_t bl0 = __float_as_uint(sW0l[nrow * PZ + tig +     8 * kt]);
                    uint32_t bh1 = __float_as_uint(sW0h[nrow * PZ + tig + 4 + 8 * kt]);
                    uint32_t bl1 = __float_as_uint(sW0l[nrow * PZ + tig + 4 + 8 * kt]);
                    mma8(acc[nn], ah, bh0, bh1);
                    mma8(acc[nn], ah, bl0, bl1);
                    mma8(acc[nn], al, bh0, bh1);
                }
            }
#pragma unroll
            for (int nn = 0; nn < 4; nn++) {
                if (nn >= NT1) break;
                int col = 8 * (wn * 4 + nn) + 2 * tig;
                float bb0 = sB0[col], bb1 = sB0[col + 1];
                sH[r0 * PZ + col    ] = tanh_fast(acc[nn][0] + bb0);
                sH[r0 * PZ + col + 1] = tanh_fast(acc[nn][1] + bb1);
                sH[r1 * PZ + col    ] = tanh_fast(acc[nn][2] + bb0);
                sH[r1 * PZ + col + 1] = tanh_fast(acc[nn][3] + bb1);
            }
        }
        __syncthreads();

        // ---- GEMM2: mu/sig heads, K=56, N=64; two n-passes of 2 tiles ----
        const bool fin = (cc >= 2);
#pragma unroll 1
        for (int np = 0; np < 2; np++) {
            float am[2][4] = {};
            float as[2][4] = {};
#pragma unroll
            for (int kt = 0; kt < 7; kt++) {
                uint32_t ah[4], al[4];
                split_tf32(sH[r0 * PZ + tig +     8 * kt], ah[0], al[0]);
                split_tf32(sH[r1 * PZ + tig +     8 * kt], ah[1], al[1]);
                split_tf32(sH[r0 * PZ + tig + 4 + 8 * kt], ah[2], al[2]);
                split_tf32(sH[r1 * PZ + tig + 4 + 8 * kt], ah[3], al[3]);
#pragma unroll
                for (int nn = 0; nn < 2; nn++) {
                    int nrow = 8 * (wn * 4 + 2 * np + nn) + gid;
                    int o0 = nrow * PZ + tig + 8 * kt;
                    int o1 = o0 + 4;
                    uint32_t bh0 = __float_as_uint(sW1h[o0]);
                    uint32_t bl0 = __float_as_uint(sW1l[o0]);
                    uint32_t bh1 = __float_as_uint(sW1h[o1]);
                    uint32_t bl1 = __float_as_uint(sW1l[o1]);
                    mma8(am[nn], ah, bh0, bh1);
                    mma8(am[nn], ah, bl0, bl1);
                    mma8(am[nn], al, bh0, bh1);
                    bh0 = __float_as_uint(sW2h[o0]);
                    bl0 = __float_as_uint(sW2l[o0]);
                    bh1 = __float_as_uint(sW2h[o1]);
                    bl1 = __float_as_uint(sW2l[o1]);
                    mma8(as[nn], ah, bh0, bh1);
                    mma8(as[nn], ah, bl0, bl1);
                    mma8(as[nn], al, bh0, bh1);
                }
            }
            // epilogue for these 16 cols
#pragma unroll
            for (int nn = 0; nn < 2; nn++) {
                int col = 8 * (wn * 4 + 2 * np + nn) + 2 * tig;
#pragma unroll
                for (int d = 0; d < 2; d++) {
                    float bm = sB1[col + d];
                    float bs = sB2[col + d];
                    {
                        float mu = am[nn][d] + bm;
                        float x  = as[nn][d] + bs;
                        float sg = fmaf(tanh_fast(0.5f * x), 0.5f, 0.5f);
                        ldp0 += __logf(sg);
                        float zn = fmaf(sZu[r0 * PZ + col + d], sg, mu);
                        sZu[r0 * PZ + col + d] = zn;
                        if (fin) ssp0 = fmaf(zn, zn, ssp0);
                    }
                    {
                        float mu = am[nn][d + 2] + bm;
                        float x  = as[nn][d + 2] + bs;
                        float sg = fmaf(tanh_fast(0.5f * x), 0.5f, 0.5f);
                        ldp1 += __logf(sg);
                        float zn = fmaf(sZu[r1 * PZ + col + d], sg, mu);
                        sZu[r1 * PZ + col + d] = zn;
                        if (fin) ssp1 = fmaf(zn, zn, ssp1);
                    }
                }
            }
        }
        __syncthreads();
    }

    // ================= write z (coalesced float4) =================
#pragma unroll
    for (int i = 0; i < 8; i++) {
        int idx = tid + TPB * i;            // 0..4095
        int row = idx >> 5, q = idx & 31;
        float4 v = (q < 16)
            ? *(const float4*)&sZ1[row * PZ + 4 * q]
            : *(const float4*)&sZ2[row * PZ + 4 * (q - 16)];
        ((float4*)out)[(size_t)(rowBase + row) * 32 + q] = v;
    }

    // ================= densities =================
    ldp0 += __shfl_xor_sync(0xffffffffu, ldp0, 1);
    ldp0 += __shfl_xor_sync(0xffffffffu, ldp0, 2);
    ldp1 += __shfl_xor_sync(0xffffffffu, ldp1, 1);
    ldp1 += __shfl_xor_sync(0xffffffffu, ldp1, 2);
    ssp0 += __shfl_xor_sync(0xffffffffu, ssp0, 1);
    ssp0 += __shfl_xor_sync(0xffffffffu, ssp0, 2);
    ssp1 += __shfl_xor_sync(0xffffffffu, ssp1, 1);
    ssp1 += __shfl_xor_sync(0xffffffffu, ssp1, 2);
    if (tig == 0) {
        sLD[wn * 128 + r0] = ldp0;
        sLD[wn * 128 + r1] = ldp1;
        sSS[wn * 128 + r0] = ssp0;
        sSS[wn * 128 + r1] = ssp1;
    }
    __syncthreads();
    if (tid < 128) {
        float l = sLD[tid] + sLD[128 + tid];
        float s = sSS[tid] + sSS[128 + tid];
        size_t base = (size_t)Brows * ZZ;
        out[base + rowBase + tid]         = -0.5f * s;
        out[base + Brows + rowBase + tid] = sQ0[tid] - l;
    }
}

extern "C" void kernel_launch(void* const* d_in, const int* in_sizes, int n_in,
                              void* d_out, int out_size)
{
    const float* mean   = (const float*)d_in[0];
    const float* logvar = (const float*)d_in[1];
    const float* eps    = (const float*)d_in[2];
    const float* W_in   = (const float*)d_in[3];
    const float* b_in   = (const float*)d_in[4];
    const float* W_mu   = (const float*)d_in[5];
    const float* b_mu   = (const float*)d_in[6];
    const float* W_sig  = (const float*)d_in[7];
    const float* b_sig  = (const float*)d_in[8];
    float* out = (float*)d_out;

    int Brows = in_sizes[0] / ZZ;

    static int attr_set = 0;
    if (!attr_set) {
        cudaFuncSetAttribute(flow_kernel, cudaFuncAttributeMaxDynamicSharedMemorySize, SMEM_BYTES);
        attr_set = 1;
    }

    presplit_kernel<<<NC, 256>>>(W_in, b_in, W_mu, b_mu, W_sig, b_sig);
    flow_kernel<<<Brows / MR, TPB, SMEM_BYTES>>>(mean, logvar, eps, out, Brows);
}

// round 8
// speedup vs baseline: 2.2366x; 2.2366x over previous
#include <cuda_runtime.h>
#include <cstdint>

// Flow1 via mma.sync m16n8k16 bf16, 3-product (hh+hl+lh) compensation.
// Weights pre-split into PACKED (bf16_hi, bf16_lo) pairs -> same bytes as fp32,
// so 2 CTAs/SM survive. H stored pre-split/packed; only z needs in-loop split.
// B=262144 rows, Z=128, ZH=64, HS=50 (padded 56), 4 couplings.
// Out: [ z (B*128) | logpz (B) | logqz (B) ] fp32.
//
// CTA = 64 rows, 256 thr = 8 warps = 4 m-groups x 2 n-halves. 2 CTAs/SM.

#define ZZ 128
#define ZH 64
#define HS 50
#define NC 4
#define TPB 256
#define MR 64
#define PZ 68      // fp32 z pitch (floats)
#define KPI 36     // k-pair pitch (uint32 words), bank-conflict-free: 36%32=4

// packed-weight word offsets (per coupling)
#define W0H 0                  // 56 n x 36 kp
#define W0L 2016
#define W1H 4032               // 64 n x 36 kp
#define W1L 6336
#define W2H 8640
#define W2L 10944
#define WTOT 13248             // words = 52992 B

// smem word offsets
#define OW   0
#define OZ1  13248             // 64 x 68 fp32
#define OZ2  17600
#define OHH  21952             // 64 x 36 packed
#define OHL  24256
#define OB   26560             // b0 @+0, b1 @+64, b2 @+128
#define OQ0  26752
#define OLD  26816             // 2*64
#define OSS  26944             // 2*64
#define SMEM_WORDS 27072
#define SMEM_BYTES (SMEM_WORDS * 4)   // 108288 -> 2 CTAs/SM

__device__ __align__(16) unsigned gW[NC][WTOT];
__device__ float gBB[NC][192];

__device__ __forceinline__ float tanh_fast(float x) {
    float r;
    asm("tanh.approx.f32 %0, %1;" : "=f"(r) : "f"(x));
    return r;
}
// d = { high: bf16(hi_elem), low: bf16(lo_elem) }  (low half = even-k element)
__device__ __forceinline__ unsigned pack2(float hi_elem, float lo_elem) {
    unsigned r;
    asm("cvt.rn.bf16x2.f32 %0, %1, %2;" : "=r"(r) : "f"(hi_elem), "f"(lo_elem));
    return r;
}
// split (x = even-k, y = odd-k) into packed hi word + packed lo word
__device__ __forceinline__ void split2(float x, float y, unsigned& h, unsigned& l) {
    h = pack2(y, x);
    float hx = __uint_as_float(h << 16);
    float hy = __uint_as_float(h & 0xFFFF0000u);
    l = pack2(y - hy, x - hx);
}
__device__ __forceinline__ void mma16(float (&d)[4], const unsigned* a,
                                      unsigned b0, unsigned b1) {
    asm volatile(
        "mma.sync.aligned.m16n8k16.row.col.f32.bf16.bf16.f32 "
        "{%0,%1,%2,%3}, {%4,%5,%6,%7}, {%8,%9}, {%0,%1,%2,%3};"
        : "+f"(d[0]), "+f"(d[1]), "+f"(d[2]), "+f"(d[3])
        : "r"(a[0]), "r"(a[1]), "r"(a[2]), "r"(a[3]), "r"(b0), "r"(b1));
}

// ---------------- pre-split kernel: pack weights as (bf16_hi, bf16_lo) ----------------
__global__ void presplit_kernel(const float* __restrict__ W_in,  const float* __restrict__ b_in,
                                const float* __restrict__ W_mu,  const float* __restrict__ b_mu,
                                const float* __restrict__ W_sig, const float* __restrict__ b_sig)
{
    const int cc = blockIdx.x;
    const int tid = threadIdx.x;
    // W0: [n<56][kp<36], source W_in[cc][n<50][k<64]
    for (int idx = tid; idx < 56 * KPI; idx += blockDim.x) {
        int n = idx / KPI, kp = idx - n * KPI;
        int k0 = 2 * kp, k1 = k0 + 1;
        float v0 = (n < HS && k0 < ZH) ? W_in[cc * HS * ZH + n * ZH + k0] : 0.0f;
        float v1 = (n < HS && k1 < ZH) ? W_in[cc * HS * ZH + n * ZH + k1] : 0.0f;
        unsigned h, l;
        split2(v0, v1, h, l);
        gW[cc][W0H + idx] = h;
        gW[cc][W0L + idx] = l;
    }
    // W1/W2: [n<64][kp<36], source [n<64][k<50]
    for (int idx = tid; idx < 64 * KPI; idx += blockDim.x) {
        int n = idx / KPI, kp = idx - n * KPI;
        int k0 = 2 * kp, k1 = k0 + 1;
        float m0 = (k0 < HS) ? W_mu [cc * ZH * HS + n * HS + k0] : 0.0f;
        float m1 = (k1 < HS) ? W_mu [cc * ZH * HS + n * HS + k1] : 0.0f;
        float s0 = (k0 < HS) ? W_sig[cc * ZH * HS + n * HS + k0] : 0.0f;
        float s1 = (k1 < HS) ? W_sig[cc * ZH * HS + n * HS + k1] : 0.0f;
        unsigned h, l;
        split2(m0, m1, h, l);
        gW[cc][W1H + idx] = h;
        gW[cc][W1L + idx] = l;
        split2(s0, s1, h, l);
        gW[cc][W2H + idx] = h;
        gW[cc][W2L + idx] = l;
    }
    if (tid < 64) {
        gBB[cc][tid]       = (tid < HS) ? b_in[cc * HS + tid] : 0.0f;
        gBB[cc][64 + tid]  = b_mu [cc * ZH + tid];
        gBB[cc][128 + tid] = b_sig[cc * ZH + tid];
    }
}

// ---------------- main kernel ----------------
__global__ void __launch_bounds__(TPB, 2)
flow_kernel(const float* __restrict__ mean,  const float* __restrict__ logvar,
            const float* __restrict__ eps,
            float* __restrict__ out, int Brows)
{
    extern __shared__ float sm[];
    unsigned* uW  = (unsigned*)(sm + OW);
    float*    sZ1 = sm + OZ1;
    float*    sZ2 = sm + OZ2;
    unsigned* uHH = (unsigned*)(sm + OHH);
    unsigned* uHL = (unsigned*)(sm + OHL);
    float*    sB0 = sm + OB;
    float*    sB1 = sm + OB + 64;
    float*    sB2 = sm + OB + 128;
    float*    sQ0 = sm + OQ0;
    float*    sLD = sm + OLD;
    float*    sSS = sm + OSS;

    const int tid  = threadIdx.x;
    const int lane = tid & 31;
    const int wid  = tid >> 5;
    const int wm   = wid & 3;          // m-group: rows 16*wm..+15
    const int wn   = wid >> 2;         // n-half
    const int gid  = lane >> 2;
    const int tig  = lane & 3;
    const int r0   = 16 * wm + gid;
    const int r1   = r0 + 8;
    const int rowBase = blockIdx.x * MR;

    // zero H k-pad (kp 28..31) once; never rewritten
    {
        int r = tid >> 2, kp = 28 + (tid & 3);
        uHH[r * KPI + kp] = 0u;
        uHL[r * KPI + kp] = 0u;
    }

    // ================= reparam =================
    {
        const int rrow = tid >> 2, p = tid & 3;
        float part = 0.0f;
#pragma unroll
        for (int j = 0; j < 8; j++) {
            int q = p + 4 * j;
            size_t g = (size_t)(rowBase + rrow) * 32 + q;
            float4 mv = ((const float4*)mean  )[g];
            float4 lv = ((const float4*)logvar)[g];
            float4 ev = ((const float4*)eps   )[g];
            float4 z4;
            z4.x = fmaf(ev.x, __expf(0.5f * lv.x), mv.x);
            z4.y = fmaf(ev.y, __expf(0.5f * lv.y), mv.y);
            z4.z = fmaf(ev.z, __expf(0.5f * lv.z), mv.z);
            z4.w = fmaf(ev.w, __expf(0.5f * lv.w), mv.w);
            part += lv.x + lv.y + lv.z + lv.w;
            part = fmaf(ev.x, ev.x, part);
            part = fmaf(ev.y, ev.y, part);
            part = fmaf(ev.z, ev.z, part);
            part = fmaf(ev.w, ev.w, part);
            if (q < 16)
                *(float4*)&sZ1[rrow * PZ + 4 * q] = z4;
            else
                *(float4*)&sZ2[rrow * PZ + 4 * (q - 16)] = z4;
        }
        part += __shfl_xor_sync(0xffffffffu, part, 1);
        part += __shfl_xor_sync(0xffffffffu, part, 2);
        if (p == 0) sQ0[rrow] = -0.5f * part;
    }

    float ldp0 = 0.f, ldp1 = 0.f, ssp0 = 0.f, ssp1 = 0.f;

    // ================= couplings =================
#pragma unroll 1
    for (int cc = 0; cc < NC; cc++) {
        // ---- stage packed split weights: raw float4 memcpy (52992 B) ----
        {
            const float4* src = (const float4*)(&gW[cc][0]);
            float4* dst = (float4*)uW;
            for (int i = tid; i < WTOT / 4; i += TPB) dst[i] = src[i];
            if (tid < 192) sm[OB + tid] = gBB[cc][tid];
        }
        __syncthreads();

        const float* sZa = (cc & 1) ? sZ2 : sZ1;
        float*       sZu = (cc & 1) ? sZ1 : sZ2;

        // ---- GEMM1: H = tanh(Za @ W0^T + b0); N=56 (tiles 0..6, wn split 4/3) ----
        {
            float acc[4][4] = {};
#pragma unroll
            for (int c = 0; c < 4; c++) {
                // A fragments from fp32 z, split to packed bf16 hi/lo
                float2 v00 = ((const float2*)&sZa[r0 * PZ])[tig +     8 * c];
                float2 v10 = ((const float2*)&sZa[r1 * PZ])[tig +     8 * c];
                float2 v01 = ((const float2*)&sZa[r0 * PZ])[tig + 4 + 8 * c];
                float2 v11 = ((const float2*)&sZa[r1 * PZ])[tig + 4 + 8 * c];
                unsigned ah[4], al[4];
                split2(v00.x, v00.y, ah[0], al[0]);
                split2(v10.x, v10.y, ah[1], al[1]);
                split2(v01.x, v01.y, ah[2], al[2]);
                split2(v11.x, v11.y, ah[3], al[3]);
#pragma unroll
                for (int nn = 0; nn < 4; nn++) {
                    int nt = wn * 4 + nn;
                    if (nt >= 7) break;
                    int nrow = 8 * nt + gid;
                    unsigned bh0 = uW[W0H + nrow * KPI + tig +     8 * c];
                    unsigned bh1 = uW[W0H + nrow * KPI + tig + 4 + 8 * c];
                    unsigned bl0 = uW[W0L + nrow * KPI + tig +     8 * c];
                    unsigned bl1 = uW[W0L + nrow * KPI + tig + 4 + 8 * c];
                    mma16(acc[nn], ah, bh0, bh1);
                    mma16(acc[nn], ah, bl0, bl1);
                    mma16(acc[nn], al, bh0, bh1);
                }
            }
            // epilogue: bias + tanh, write H pre-split/packed
#pragma unroll
            for (int nn = 0; nn < 4; nn++) {
                int nt = wn * 4 + nn;
                if (nt >= 7) break;
                int col = 8 * nt + 2 * tig;
                float bb0 = sB0[col], bb1 = sB0[col + 1];
                float t00 = tanh_fast(acc[nn][0] + bb0);
                float t01 = tanh_fast(acc[nn][1] + bb1);
                float t10 = tanh_fast(acc[nn][2] + bb0);
                float t11 = tanh_fast(acc[nn][3] + bb1);
                int kp = 4 * nt + tig;
                unsigned h, l;
                split2(t00, t01, h, l);
                uHH[r0 * KPI + kp] = h;
                uHL[r0 * KPI + kp] = l;
                split2(t10, t11, h, l);
                uHH[r1 * KPI + kp] = h;
                uHL[r1 * KPI + kp] = l;
            }
        }
        __syncthreads();

        // ---- GEMM2: mu/sig heads; K=64 (padded), N=64: 4 tiles/warp ----
        {
            float am[4][4] = {};
            float as2[4][4] = {};
#pragma unroll
            for (int c = 0; c < 4; c++) {
                unsigned ah[4], al[4];
                ah[0] = uHH[r0 * KPI + tig +     8 * c];
                ah[1] = uHH[r1 * KPI + tig +     8 * c];
                ah[2] = uHH[r0 * KPI + tig + 4 + 8 * c];
                ah[3] = uHH[r1 * KPI + tig + 4 + 8 * c];
                al[0] = uHL[r0 * KPI + tig +     8 * c];
                al[1] = uHL[r1 * KPI + tig +     8 * c];
                al[2] = uHL[r0 * KPI + tig + 4 + 8 * c];
                al[3] = uHL[r1 * KPI + tig + 4 + 8 * c];
#pragma unroll
                for (int nn = 0; nn < 4; nn++) {
                    int nrow = 8 * (wn * 4 + nn) + gid;
                    unsigned bh0 = uW[W1H + nrow * KPI + tig +     8 * c];
                    unsigned bh1 = uW[W1H + nrow * KPI + tig + 4 + 8 * c];
                    unsigned bl0 = uW[W1L + nrow * KPI + tig +     8 * c];
                    unsigned bl1 = uW[W1L + nrow * KPI + tig + 4 + 8 * c];
                    mma16(am[nn], ah, bh0, bh1);
                    mma16(am[nn], ah, bl0, bl1);
                    mma16(am[nn], al, bh0, bh1);
                    bh0 = uW[W2H + nrow * KPI + tig +     8 * c];
                    bh1 = uW[W2H + nrow * KPI + tig + 4 + 8 * c];
                    bl0 = uW[W2L + nrow * KPI + tig +     8 * c];
                    bl1 = uW[W2L + nrow * KPI + tig + 4 + 8 * c];
                    mma16(as2[nn], ah, bh0, bh1);
                    mma16(as2[nn], ah, bl0, bl1);
                    mma16(as2[nn], al, bh0, bh1);
                }
            }
            // epilogue: sig, z update, logdet
            const bool fin = (cc >= 2);
#pragma unroll
            for (int nn = 0; nn < 4; nn++) {
                int col = 8 * (wn * 4 + nn) + 2 * tig;
#pragma unroll
                for (int d = 0; d < 2; d++) {
                    float bm = sB1[col + d];
                    float bs = sB2[col + d];
                    {
                        float mu = am[nn][d] + bm;
                        float x  = as2[nn][d] + bs;
                        float sg = fmaf(tanh_fast(0.5f * x), 0.5f, 0.5f);
                        ldp0 += __logf(sg);
                        float zn = fmaf(sZu[r0 * PZ + col + d], sg, mu);
                        sZu[r0 * PZ + col + d] = zn;
                        if (fin) ssp0 = fmaf(zn, zn, ssp0);
                    }
                    {
                        float mu = am[nn][d + 2] + bm;
                        float x  = as2[nn][d + 2] + bs;
                        float sg = fmaf(tanh_fast(0.5f * x), 0.5f, 0.5f);
                        ldp1 += __logf(sg);
                        float zn = fmaf(sZu[r1 * PZ + col + d], sg, mu);
                        sZu[r1 * PZ + col + d] = zn;
                        if (fin) ssp1 = fmaf(zn, zn, ssp1);
                    }
                }
            }
        }
        __syncthreads();
    }

    // ================= write z (coalesced float4) =================
#pragma unroll
    for (int i = 0; i < 8; i++) {
        int idx = tid + TPB * i;            // 0..2047
        int row = idx >> 5, q = idx & 31;
        float4 v = (q < 16)
            ? *(const float4*)&sZ1[row * PZ + 4 * q]
            : *(const float4*)&sZ2[row * PZ + 4 * (q - 16)];
        ((float4*)out)[(size_t)(rowBase + row) * 32 + q] = v;
    }

    // ================= densities =================
    ldp0 += __shfl_xor_sync(0xffffffffu, ldp0, 1);
    ldp0 += __shfl_xor_sync(0xffffffffu, ldp0, 2);
    ldp1 += __shfl_xor_sync(0xffffffffu, ldp1, 1);
    ldp1 += __shfl_xor_sync(0xffffffffu, ldp1, 2);
    ssp0 += __shfl_xor_sync(0xffffffffu, ssp0, 1);
    ssp0 += __shfl_xor_sync(0xffffffffu, ssp0, 2);
    ssp1 += __shfl_xor_sync(0xffffffffu, ssp1, 1);
    ssp1 += __shfl_xor_sync(0xffffffffu, ssp1, 2);
    if (tig == 0) {
        sLD[wn * 64 + r0] = ldp0;
        sLD[wn * 64 + r1] = ldp1;
        sSS[wn * 64 + r0] = ssp0;
        sSS[wn * 64 + r1] = ssp1;
    }
    __syncthreads();
    if (tid < 64) {
        float l = sLD[tid] + sLD[64 + tid];
        float s = sSS[tid] + sSS[64 + tid];
        size_t base = (size_t)Brows * ZZ;
        out[base + rowBase + tid]         = -0.5f * s;
        out[base + Brows + rowBase + tid] = sQ0[tid] - l;
    }
}

extern "C" void kernel_launch(void* const* d_in, const int* in_sizes, int n_in,
                              void* d_out, int out_size)
{
    const float* mean   = (const float*)d_in[0];
    const float* logvar = (const float*)d_in[1];
    const float* eps    = (const float*)d_in[2];
    const float* W_in   = (const float*)d_in[3];
    const float* b_in   = (const float*)d_in[4];
    const float* W_mu   = (const float*)d_in[5];
    const float* b_mu   = (const float*)d_in[6];
    const float* W_sig  = (const float*)d_in[7];
    const float* b_sig  = (const float*)d_in[8];
    float* out = (float*)d_out;

    int Brows = in_sizes[0] / ZZ;

    static int attr_set = 0;
    if (!attr_set) {
        cudaFuncSetAttribute(flow_kernel, cudaFuncAttributeMaxDynamicSharedMemorySize, SMEM_BYTES);
        attr_set = 1;
    }

    presplit_kernel<<<NC, 256>>>(W_in, b_in, W_mu, b_mu, W_sig, b_sig);
    flow_kernel<<<Brows / MR, TPB, SMEM_BYTES>>>(mean, logvar, eps, out, Brows);
}